// round 13
// baseline (speedup 1.0000x reference)
#include <cuda_runtime.h>
#include <cuda_bf16.h>
#include <cuda_fp16.h>
#include <math.h>
#include <stdint.h>

// ---------------------------------------------------------------------------
// MoE FFN top-2/8, H=1024, I=4096, T<=8192, fp32 in/out.
// R13: occupancy push #2. CTA tile 128x64, warp tile 32x32 (32 acc regs),
// __launch_bounds__(256,3) -> 3 CTAs/SM = 6 warps/SMSP. 3-buffer cp.async
// ring, 1 barrier per chunk. Kahan gate, fused dual weight split.
// Launch order: split_x(0), split_w_dual(1), gate(2), gemm1(3 = ncu target),
//               gemm2(4), combine(5).
// ---------------------------------------------------------------------------

#define HID   1024
#define INTER 4096
#define NEXP  8
#define TMAX  8192
#define NSLOT (2 * TMAX)

#define WCNT ((size_t)NEXP * (size_t)INTER * (size_t)HID)
#define XOFF ((size_t)TMAX * (size_t)HID)
#define HOFF ((size_t)NSLOT * (size_t)INTER)

__device__ __half d_xs[XOFF];         // x fp16
__device__ __half d_w1h[WCNT];        // W1 fp16
__device__ __half d_w2h[WCNT];        // W2 fp16
__device__ __half d_hs[HOFF];         // h fp16
__device__ float  d_y[(size_t)NSLOT * (size_t)HID];
__device__ float  d_slot_w[NSLOT];
__device__ int    d_slot_list[NEXP * TMAX];
__device__ int    d_counts[NEXP];

// ------------------------------ PTX helpers --------------------------------

__device__ __forceinline__ uint32_t smem_u32(const void* p) {
    uint32_t a;
    asm("{ .reg .u64 t; cvta.to.shared.u64 t, %1; cvt.u32.u64 %0, t; }"
        : "=r"(a) : "l"(p));
    return a;
}

__device__ __forceinline__ void cp16(uint32_t saddr, const void* g) {
    asm volatile("cp.async.cg.shared.global [%0], [%1], 16;"
                 :: "r"(saddr), "l"(g));
}
#define CP_COMMIT() asm volatile("cp.async.commit_group;" ::: "memory")
#define CP_WAIT(N)  asm volatile("cp.async.wait_group %0;" :: "n"(N) : "memory")

__device__ __forceinline__ void ldm_x4(uint32_t* r, uint32_t addr) {
    asm volatile("ldmatrix.sync.aligned.m8n8.x4.shared.b16 {%0,%1,%2,%3}, [%4];"
                 : "=r"(r[0]), "=r"(r[1]), "=r"(r[2]), "=r"(r[3]) : "r"(addr));
}

__device__ __forceinline__ void mma16816(float* c, const uint32_t* a,
                                         uint32_t b0, uint32_t b1) {
    asm volatile(
        "mma.sync.aligned.m16n8k16.row.col.f32.f16.f16.f32 "
        "{%0,%1,%2,%3}, {%4,%5,%6,%7}, {%8,%9}, {%0,%1,%2,%3};"
        : "+f"(c[0]), "+f"(c[1]), "+f"(c[2]), "+f"(c[3])
        : "r"(a[0]), "r"(a[1]), "r"(a[2]), "r"(a[3]), "r"(b0), "r"(b1));
}

// ---------------------------- split kernels --------------------------------

__global__ void split_kernel(const float* __restrict__ src,
                             __half* __restrict__ dst, size_t n4,
                             int zero_counts) {
    if (zero_counts && blockIdx.x == 0 && threadIdx.x < NEXP)
        d_counts[threadIdx.x] = 0;
    size_t i = (size_t)blockIdx.x * blockDim.x + threadIdx.x;
    if (i >= n4) return;
    float4 v = ((const float4*)src)[i];
    ushort4 hv = make_ushort4(__half_as_ushort(__float2half_rn(v.x)),
                              __half_as_ushort(__float2half_rn(v.y)),
                              __half_as_ushort(__float2half_rn(v.z)),
                              __half_as_ushort(__float2half_rn(v.w)));
    *(ushort4*)(dst + 4 * i) = hv;
}

__global__ void split_w_dual(const float* __restrict__ s1,
                             __half* __restrict__ d1,
                             const float* __restrict__ s2,
                             __half* __restrict__ d2, size_t n4) {
    size_t i = (size_t)blockIdx.x * blockDim.x + threadIdx.x;
    const float* src;
    __half* dst;
    size_t j;
    if (i < n4)          { src = s1; dst = d1; j = i; }
    else if (i < 2 * n4) { src = s2; dst = d2; j = i - n4; }
    else return;
    float4 v = ((const float4*)src)[j];
    ushort4 hv = make_ushort4(__half_as_ushort(__float2half_rn(v.x)),
                              __half_as_ushort(__float2half_rn(v.y)),
                              __half_as_ushort(__float2half_rn(v.z)),
                              __half_as_ushort(__float2half_rn(v.w)));
    *(ushort4*)(dst + 4 * j) = hv;
}

// ------------------------------ gating -------------------------------------

__global__ void gate_kernel(const float* __restrict__ x,
                            const float* __restrict__ gw, int T) {
    int warp = (blockIdx.x * blockDim.x + threadIdx.x) >> 5;
    int lane = threadIdx.x & 31;
    if (warp >= T) return;
    const float* xr = x + (size_t)warp * HID;

    float acc[NEXP], cmp[NEXP];
#pragma unroll
    for (int e = 0; e < NEXP; e++) { acc[e] = 0.0f; cmp[e] = 0.0f; }
#pragma unroll 4
    for (int i = lane; i < HID; i += 32) {
        float xv = xr[i];
#pragma unroll
        for (int e = 0; e < NEXP; e++) {
            float prod = xv * gw[e * HID + i];
            float y = prod - cmp[e];
            float t = acc[e] + y;
            cmp[e] = (t - acc[e]) - y;
            acc[e] = t;
        }
    }
#pragma unroll
    for (int e = 0; e < NEXP; e++) {
#pragma unroll
        for (int o = 16; o > 0; o >>= 1)
            acc[e] += __shfl_down_sync(0xffffffffu, acc[e], o);
    }
    if (lane == 0) {
        float bv = -1e30f, sv = -1e30f;
        int bi = 0, si = 0;
#pragma unroll
        for (int e = 0; e < NEXP; e++) {
            float val = acc[e];
            if (val > bv) { sv = bv; si = bi; bv = val; bi = e; }
            else if (val > sv) { sv = val; si = e; }
        }
        float e1 = expf(sv - bv);
        float s = 1.0f + e1;
        d_slot_w[2 * warp + 0] = 1.0f / s;
        d_slot_w[2 * warp + 1] = e1 / s;
        int p0 = atomicAdd(&d_counts[bi], 1);
        d_slot_list[bi * TMAX + p0] = 2 * warp;
        int p1 = atomicAdd(&d_counts[si], 1);
        d_slot_list[si * TMAX + p1] = 2 * warp + 1;
    }
}

// ----------------------------- HMMA GEMM -----------------------------------
// CTA tile 128(M) x 64(N), BK=64 fp16 (128 B rows, xor-8 swizzle).
// 8 warps of 32x32 (4 in M x 2 in N), 3 CTAs/SM. 3 smem buffers,
// depth-2 cp.async in flight, 1 barrier per chunk.

#define BM 128
#define BN 64
#define BK 64

#define SM_BUF 1024
#define AREG   16384                  // A: 128 rows * 128 B
#define BOFF   AREG                   // B region offset
#define BUFSZ  (AREG + 8192)          // 24576: + 64 rows * 128 B
#define NBUF   3
#define SMEM_TOTAL (SM_BUF + NBUF * BUFSZ)   // 74752 B; x3 CTAs = 219 KB/SM

template <int KDIM, int NDIM, bool FFN1>
__global__ void __launch_bounds__(256, 3)
moe_gemm_mma(const float* __restrict__ Bv)   // bias [NEXP][NDIM]
{
    constexpr int NC = KDIM / BK;     // 16 or 64

    const int e   = blockIdx.z;
    const int cnt = d_counts[e];
    const int r0  = blockIdx.y * BM;
    if (r0 >= cnt) return;
    const int n0  = blockIdx.x * BN;

    const __half* __restrict__ Wbase = FFN1 ? d_w1h : d_w2h;
    const __half* __restrict__ Abase = FFN1 ? d_xs : d_hs;

    extern __shared__ __align__(128) char smem[];
    const uint32_t sb = smem_u32(smem);
    const int tid = threadIdx.x;

    int* Srow = (int*)smem;
    if (tid < BM) {
        int idx = r0 + tid;
        Srow[tid] = (idx < cnt) ? d_slot_list[e * TMAX + idx] : -1;
    }
    __syncthreads();

    // ---- loader precompute ------------------------------------------------
    // A: 128 rows, row = tid>>1, 4 x 16B chunks at (tid&1)*4.
    const int arow_ld = tid >> 1;
    const int ach0    = (tid & 1) * 4;
    const uint32_t a_dst = (uint32_t)arow_ld * 128u;
    const int arx = arow_ld & 7;
    // B: 64 rows, row = tid>>2, 2 x 16B chunks at (tid&3)*2.
    const int brow_ld = tid >> 2;
    const int bch0    = (tid & 3) * 2;
    const uint32_t b_dst = BOFF + (uint32_t)brow_ld * 128u;
    const int brx = brow_ld & 7;

    int s_ld = Srow[arow_ld];
    const __half* aptr;
    if (FFN1) {
        int tok = (s_ld < 0) ? 0 : (s_ld >> 1);
        aptr = Abase + (size_t)tok * KDIM;
    } else {
        aptr = Abase + (size_t)(s_ld < 0 ? 0 : s_ld) * KDIM;
    }
    const __half* bptr = Wbase + ((size_t)e * NDIM + n0 + brow_ld) * KDIM;

    auto load_chunk = [&](int c) {
        const uint32_t dbuf = sb + SM_BUF + (uint32_t)(c % NBUF) * BUFSZ;
        const int koff = c * BK;
#pragma unroll
        for (int i = 0; i < 4; i++) {
            int ch = ach0 + i;
            cp16(dbuf + a_dst + (uint32_t)((ch ^ arx) << 4),
                 aptr + koff + ch * 8);
        }
#pragma unroll
        for (int i = 0; i < 2; i++) {
            int ch = bch0 + i;
            cp16(dbuf + b_dst + (uint32_t)((ch ^ brx) << 4),
                 bptr + koff + ch * 8);
        }
        CP_COMMIT();
    };

    // ---- compute precompute ----------------------------------------------
    const int wid = tid >> 5, l = tid & 31;
    const int wm = wid >> 1;           // 0..3  M quarter (32 rows)
    const int wn = wid & 1;            // 0..1  N half (32 cols)
    const int g  = l >> 2, tg = l & 3;

    const int arow0 = wm * 32 + (l & 15);
    const uint32_t a_rowoff = (uint32_t)arow0 * 128u;
    const int axr = arow0 & 7;
    const int a_chsel = l >> 4;

    const int brow0 = wn * 32 + ((l >> 4) << 3) + (l & 7);
    const uint32_t b_rowoff = BOFF + (uint32_t)brow0 * 128u;
    const int bxr = brow0 & 7;
    const int b_chsel = (l >> 3) & 1;

    float acc[2][4][4];
#pragma unroll
    for (int a = 0; a < 2; a++)
#pragma unroll
        for (int b = 0; b < 4; b++)
#pragma unroll
            for (int q = 0; q < 4; q++) acc[a][b][q] = 0.0f;

    // depth-2 preload (3-buffer ring)
    load_chunk(0);
    load_chunk(1);

    for (int c = 0; c < NC; c++) {
        if (c + 1 < NC) { CP_WAIT(1); }
        else            { CP_WAIT(0); }
        __syncthreads();
        if (c + 2 < NC) load_chunk(c + 2);

        const uint32_t sbuf = sb + SM_BUF + (uint32_t)(c % NBUF) * BUFSZ;
#pragma unroll
        for (int ks = 0; ks < BK / 16; ks++) {
            uint32_t ah[2][4];
            const uint32_t aoff =
                (uint32_t)(((2 * ks + a_chsel) ^ axr) << 4);
#pragma unroll
            for (int mi = 0; mi < 2; mi++) {
                ldm_x4(ah[mi], sbuf + a_rowoff + (uint32_t)mi * 2048u + aoff);
            }
            const uint32_t boff =
                (uint32_t)(((2 * ks + b_chsel) ^ bxr) << 4);
#pragma unroll
            for (int jp = 0; jp < 2; jp++) {
                uint32_t bh[4];
                ldm_x4(bh, sbuf + b_rowoff + (uint32_t)jp * 2048u + boff);
#pragma unroll
                for (int mi = 0; mi < 2; mi++) {
                    mma16816(acc[mi][2 * jp],     ah[mi], bh[0], bh[1]);
                    mma16816(acc[mi][2 * jp + 1], ah[mi], bh[2], bh[3]);
                }
            }
        }
    }

    // ---- epilogue ---------------------------------------------------------
    const float* bias = Bv + (size_t)e * NDIM;
#pragma unroll
    for (int mi = 0; mi < 2; mi++) {
        const int lr0 = wm * 32 + mi * 16 + g;
        const int slotA = Srow[lr0];
        const int slotB = Srow[lr0 + 8];
#pragma unroll
        for (int nj = 0; nj < 4; nj++) {
            const int col = n0 + wn * 32 + nj * 8 + 2 * tg;
            const float b0 = bias[col], b1 = bias[col + 1];
            if (FFN1) {
                if (slotA >= 0) {
                    float v0 = acc[mi][nj][0] + b0;
                    float v1 = acc[mi][nj][1] + b1;
                    v0 = 0.5f * v0 * (1.0f + erff(v0 * 0.7071067811865475f));
                    v1 = 0.5f * v1 * (1.0f + erff(v1 * 0.7071067811865475f));
                    *(__half2*)(d_hs + (size_t)slotA * INTER + col) =
                        __floats2half2_rn(v0, v1);
                }
                if (slotB >= 0) {
                    float v0 = acc[mi][nj][2] + b0;
                    float v1 = acc[mi][nj][3] + b1;
                    v0 = 0.5f * v0 * (1.0f + erff(v0 * 0.7071067811865475f));
                    v1 = 0.5f * v1 * (1.0f + erff(v1 * 0.7071067811865475f));
                    *(__half2*)(d_hs + (size_t)slotB * INTER + col) =
                        __floats2half2_rn(v0, v1);
                }
            } else {
                if (slotA >= 0) {
                    float wmul = d_slot_w[slotA];
                    float2 o;
                    o.x = (acc[mi][nj][0] + b0) * wmul;
                    o.y = (acc[mi][nj][1] + b1) * wmul;
                    *(float2*)(d_y + (size_t)slotA * HID + col) = o;
                }
                if (slotB >= 0) {
                    float wmul = d_slot_w[slotB];
                    float2 o;
                    o.x = (acc[mi][nj][2] + b0) * wmul;
                    o.y = (acc[mi][nj][3] + b1) * wmul;
                    *(float2*)(d_y + (size_t)slotB * HID + col) = o;
                }
            }
        }
    }
}

// ------------------------------ combine ------------------------------------

__global__ void combine_kernel(float* __restrict__ out, int T) {
    int i = blockIdx.x * blockDim.x + threadIdx.x;
    int total = T * (HID / 4);
    if (i >= total) return;
    int h4 = i & (HID / 4 - 1);
    int t  = i >> 8;
    const float4* y4 = (const float4*)d_y;
    float4 a = y4[(size_t)(2 * t) * (HID / 4) + h4];
    float4 b = y4[(size_t)(2 * t + 1) * (HID / 4) + h4];
    float4 r;
    r.x = a.x + b.x; r.y = a.y + b.y; r.z = a.z + b.z; r.w = a.w + b.w;
    ((float4*)out)[i] = r;
}

// ------------------------------- launch ------------------------------------

extern "C" void kernel_launch(void* const* d_in, const int* in_sizes, int n_in,
                              void* d_out, int out_size) {
    const float* x  = (const float*)d_in[0];
    const float* gw = (const float*)d_in[1];
    const float* W1 = (const float*)d_in[2];
    const float* b1 = (const float*)d_in[3];
    const float* W2 = (const float*)d_in[4];
    const float* b2 = (const float*)d_in[5];
    float* out = (float*)d_out;

    int T = in_sizes[0] / HID;

    cudaFuncSetAttribute(moe_gemm_mma<HID, INTER, true>,
                         cudaFuncAttributeMaxDynamicSharedMemorySize,
                         SMEM_TOTAL);
    cudaFuncSetAttribute(moe_gemm_mma<INTER, HID, false>,
                         cudaFuncAttributeMaxDynamicSharedMemorySize,
                         SMEM_TOTAL);

    __half* dxs; cudaGetSymbolAddress((void**)&dxs, d_xs);
    __half* dw1; cudaGetSymbolAddress((void**)&dw1, d_w1h);
    __half* dw2; cudaGetSymbolAddress((void**)&dw2, d_w2h);

    size_t nx4 = (size_t)T * HID / 4;
    size_t nw4 = WCNT / 4;
    int mtiles = (T + BM - 1) / BM;

    // launch 0: x -> fp16 (+ zero counts)
    split_kernel<<<(unsigned)((nx4 + 255) / 256), 256>>>(x, dxs, nx4, 1);
    // launch 1: W1 & W2 -> fp16 (fused)
    split_w_dual<<<(unsigned)((2 * nw4 + 255) / 256), 256>>>(W1, dw1, W2, dw2,
                                                             nw4);
    // launch 2: gating
    gate_kernel<<<(T + 7) / 8, 256>>>(x, gw, T);
    // launch 3: GEMM1  (ncu target)
    dim3 g1(INTER / BN, mtiles, NEXP);
    moe_gemm_mma<HID, INTER, true><<<g1, 256, SMEM_TOTAL>>>(b1);
    // launch 4: GEMM2
    dim3 g2(HID / BN, mtiles, NEXP);
    moe_gemm_mma<INTER, HID, false><<<g2, 256, SMEM_TOTAL>>>(b2);
    // launch 5: combine
    combine_kernel<<<(T * (HID / 4) + 255) / 256, 256>>>(out, T);
}

// round 14
// speedup vs baseline: 1.1375x; 1.1375x over previous
#include <cuda_runtime.h>
#include <cuda_bf16.h>
#include <cuda_fp16.h>
#include <math.h>
#include <stdint.h>

// ---------------------------------------------------------------------------
// MoE FFN top-2/8, H=1024, I=4096, T<=8192, fp32 in/out.
// R14: R11 GEMM inner loop (128x128 CTA, 64x32 warp tile, 2 CTAs/SM,
// 3-buffer cp.async ring, 1 barrier/chunk — best measured) wrapped in a
// PERSISTENT work-stealing scheduler (296 CTAs pull tile ids from a device
// counter; no empty CTAs, no per-expert wave quantization).
// + Kahan-fp32 gate, fused dual weight split (validated R12).
// Launch order: split_x(0), split_w_dual(1), gate(2), gemm1(3 = ncu target),
//               gemm2(4), combine(5).
// ---------------------------------------------------------------------------

#define HID   1024
#define INTER 4096
#define NEXP  8
#define TMAX  8192
#define NSLOT (2 * TMAX)

#define WCNT ((size_t)NEXP * (size_t)INTER * (size_t)HID)
#define XOFF ((size_t)TMAX * (size_t)HID)
#define HOFF ((size_t)NSLOT * (size_t)INTER)

__device__ __half d_xs[XOFF];         // x fp16
__device__ __half d_w1h[WCNT];        // W1 fp16
__device__ __half d_w2h[WCNT];        // W2 fp16
__device__ __half d_hs[HOFF];         // h fp16
__device__ float  d_y[(size_t)NSLOT * (size_t)HID];
__device__ float  d_slot_w[NSLOT];
__device__ int    d_slot_list[NEXP * TMAX];
__device__ int    d_counts[NEXP];
__device__ int    d_work1;            // persistent tile counter, GEMM1
__device__ int    d_work2;            // persistent tile counter, GEMM2

// ------------------------------ PTX helpers --------------------------------

__device__ __forceinline__ uint32_t smem_u32(const void* p) {
    uint32_t a;
    asm("{ .reg .u64 t; cvta.to.shared.u64 t, %1; cvt.u32.u64 %0, t; }"
        : "=r"(a) : "l"(p));
    return a;
}

__device__ __forceinline__ void cp16(uint32_t saddr, const void* g) {
    asm volatile("cp.async.cg.shared.global [%0], [%1], 16;"
                 :: "r"(saddr), "l"(g));
}
#define CP_COMMIT() asm volatile("cp.async.commit_group;" ::: "memory")
#define CP_WAIT(N)  asm volatile("cp.async.wait_group %0;" :: "n"(N) : "memory")

__device__ __forceinline__ void ldm_x4(uint32_t* r, uint32_t addr) {
    asm volatile("ldmatrix.sync.aligned.m8n8.x4.shared.b16 {%0,%1,%2,%3}, [%4];"
                 : "=r"(r[0]), "=r"(r[1]), "=r"(r[2]), "=r"(r[3]) : "r"(addr));
}

__device__ __forceinline__ void mma16816(float* c, const uint32_t* a,
                                         uint32_t b0, uint32_t b1) {
    asm volatile(
        "mma.sync.aligned.m16n8k16.row.col.f32.f16.f16.f32 "
        "{%0,%1,%2,%3}, {%4,%5,%6,%7}, {%8,%9}, {%0,%1,%2,%3};"
        : "+f"(c[0]), "+f"(c[1]), "+f"(c[2]), "+f"(c[3])
        : "r"(a[0]), "r"(a[1]), "r"(a[2]), "r"(a[3]), "r"(b0), "r"(b1));
}

// ---------------------------- split kernels --------------------------------

__global__ void split_kernel(const float* __restrict__ src,
                             __half* __restrict__ dst, size_t n4,
                             int zero_state) {
    if (zero_state && blockIdx.x == 0 && threadIdx.x < NEXP + 2) {
        if (threadIdx.x < NEXP) d_counts[threadIdx.x] = 0;
        else if (threadIdx.x == NEXP) d_work1 = 0;
        else d_work2 = 0;
    }
    size_t i = (size_t)blockIdx.x * blockDim.x + threadIdx.x;
    if (i >= n4) return;
    float4 v = ((const float4*)src)[i];
    ushort4 hv = make_ushort4(__half_as_ushort(__float2half_rn(v.x)),
                              __half_as_ushort(__float2half_rn(v.y)),
                              __half_as_ushort(__float2half_rn(v.z)),
                              __half_as_ushort(__float2half_rn(v.w)));
    *(ushort4*)(dst + 4 * i) = hv;
}

__global__ void split_w_dual(const float* __restrict__ s1,
                             __half* __restrict__ d1,
                             const float* __restrict__ s2,
                             __half* __restrict__ d2, size_t n4) {
    size_t i = (size_t)blockIdx.x * blockDim.x + threadIdx.x;
    const float* src;
    __half* dst;
    size_t j;
    if (i < n4)          { src = s1; dst = d1; j = i; }
    else if (i < 2 * n4) { src = s2; dst = d2; j = i - n4; }
    else return;
    float4 v = ((const float4*)src)[j];
    ushort4 hv = make_ushort4(__half_as_ushort(__float2half_rn(v.x)),
                              __half_as_ushort(__float2half_rn(v.y)),
                              __half_as_ushort(__float2half_rn(v.z)),
                              __half_as_ushort(__float2half_rn(v.w)));
    *(ushort4*)(dst + 4 * j) = hv;
}

// ------------------------------ gating -------------------------------------

__global__ void gate_kernel(const float* __restrict__ x,
                            const float* __restrict__ gw, int T) {
    int warp = (blockIdx.x * blockDim.x + threadIdx.x) >> 5;
    int lane = threadIdx.x & 31;
    if (warp >= T) return;
    const float* xr = x + (size_t)warp * HID;

    float acc[NEXP], cmp[NEXP];
#pragma unroll
    for (int e = 0; e < NEXP; e++) { acc[e] = 0.0f; cmp[e] = 0.0f; }
#pragma unroll 4
    for (int i = lane; i < HID; i += 32) {
        float xv = xr[i];
#pragma unroll
        for (int e = 0; e < NEXP; e++) {
            float prod = xv * gw[e * HID + i];
            float y = prod - cmp[e];
            float t = acc[e] + y;
            cmp[e] = (t - acc[e]) - y;
            acc[e] = t;
        }
    }
#pragma unroll
    for (int e = 0; e < NEXP; e++) {
#pragma unroll
        for (int o = 16; o > 0; o >>= 1)
            acc[e] += __shfl_down_sync(0xffffffffu, acc[e], o);
    }
    if (lane == 0) {
        float bv = -1e30f, sv = -1e30f;
        int bi = 0, si = 0;
#pragma unroll
        for (int e = 0; e < NEXP; e++) {
            float val = acc[e];
            if (val > bv) { sv = bv; si = bi; bv = val; bi = e; }
            else if (val > sv) { sv = val; si = e; }
        }
        float e1 = expf(sv - bv);
        float s = 1.0f + e1;
        d_slot_w[2 * warp + 0] = 1.0f / s;
        d_slot_w[2 * warp + 1] = e1 / s;
        int p0 = atomicAdd(&d_counts[bi], 1);
        d_slot_list[bi * TMAX + p0] = 2 * warp;
        int p1 = atomicAdd(&d_counts[si], 1);
        d_slot_list[si * TMAX + p1] = 2 * warp + 1;
    }
}

// ----------------------------- HMMA GEMM -----------------------------------
// Persistent: each CTA pulls tile ids (expert, mtile, ntile) from a device
// counter. Inner loop identical to R11: CTA tile 128x128, BK=64, 8 warps of
// 64x32, 3-buffer cp.async ring, 1 barrier per chunk, 2 CTAs/SM.

#define BM 128
#define BN 128
#define BK 64

#define SM_BUF 1024
#define AREG   16384
#define BOFF   AREG
#define BUFSZ  (AREG + 16384)         // 32768
#define NBUF   3
#define SMEM_TOTAL (SM_BUF + NBUF * BUFSZ)   // 99328 B; x2 CTAs = 194 KB/SM

#define NPERSIST 296                  // 2 CTAs/SM x 148 SMs

template <int KDIM, int NDIM, bool FFN1>
__global__ void __launch_bounds__(256, 2)
moe_gemm_mma(const float* __restrict__ Bv)   // bias [NEXP][NDIM]
{
    constexpr int NC = KDIM / BK;
    constexpr int NT = NDIM / BN;

    const __half* __restrict__ Wbase = FFN1 ? d_w1h : d_w2h;
    const __half* __restrict__ Abase = FFN1 ? d_xs : d_hs;

    extern __shared__ __align__(128) char smem[];
    const uint32_t sb = smem_u32(smem);
    const int tid = threadIdx.x;

    int* Srow   = (int*)smem;                 // [0, 512)
    int* s_tile = (int*)(smem + 512);

    // per-expert M-tile counts + total (all threads compute identically)
    int mt[NEXP];
    int total = 0;
#pragma unroll
    for (int e = 0; e < NEXP; e++) {
        mt[e] = (d_counts[e] + BM - 1) / BM;
        total += mt[e] * NT;
    }
    int* counter = FFN1 ? &d_work1 : &d_work2;

    // ---- compute-side constants (tile-independent) ------------------------
    const int wid = tid >> 5, l = tid & 31;
    const int wm = wid >> 2;
    const int wn = wid & 3;
    const int g  = l >> 2, tg = l & 3;

    const int arow0 = wm * 64 + (l & 15);
    const uint32_t a_rowoff = (uint32_t)arow0 * 128u;
    const int axr = arow0 & 7;
    const int a_chsel = l >> 4;

    const int brow0 = wn * 32 + ((l >> 4) << 3) + (l & 7);
    const uint32_t b_rowoff = BOFF + (uint32_t)brow0 * 128u;
    const int bxr = brow0 & 7;
    const int b_chsel = (l >> 3) & 1;

    // loader constants
    const int lrow = tid >> 1;
    const int ach0 = (tid & 1) * 4;
    const uint32_t row_dst = (uint32_t)lrow * 128u;
    const int rx = lrow & 7;

    while (true) {
        if (tid == 0) *s_tile = atomicAdd(counter, 1);
        __syncthreads();                  // also: prev epilogue done w/ Srow
        int t = *s_tile;
        if (t >= total) break;

        // map t -> (e, m, n); m fastest so consecutive tiles share B (n0)
        int e = 0;
#pragma unroll
        for (int k = 0; k < NEXP - 1; k++) {
            int sz = mt[e] * NT;
            if (t >= sz) { t -= sz; e++; }
        }
        const int m  = t % mt[e];
        const int n  = t / mt[e];
        const int r0 = m * BM;
        const int n0 = n * BN;
        const int cnt = d_counts[e];

        if (tid < BM) {
            int idx = r0 + tid;
            Srow[tid] = (idx < cnt) ? d_slot_list[e * TMAX + idx] : -1;
        }
        __syncthreads();

        // ---- per-tile loader pointers -------------------------------------
        int s_ld = Srow[lrow];
        const __half* aptr;
        if (FFN1) {
            int tok = (s_ld < 0) ? 0 : (s_ld >> 1);
            aptr = Abase + (size_t)tok * KDIM;
        } else {
            aptr = Abase + (size_t)(s_ld < 0 ? 0 : s_ld) * KDIM;
        }
        const __half* bptr = Wbase + ((size_t)e * NDIM + n0 + lrow) * KDIM;

        auto load_chunk = [&](int c) {
            const uint32_t dbuf = sb + SM_BUF + (uint32_t)(c % NBUF) * BUFSZ;
            const int koff = c * BK;
#pragma unroll
            for (int i = 0; i < 4; i++) {
                int ch = ach0 + i;
                uint32_t sw = (uint32_t)((ch ^ rx) << 4);
                cp16(dbuf + row_dst + sw, aptr + koff + ch * 8);
                cp16(dbuf + BOFF + row_dst + sw, bptr + koff + ch * 8);
            }
            CP_COMMIT();
        };

        float acc[4][4][4];
#pragma unroll
        for (int a = 0; a < 4; a++)
#pragma unroll
            for (int b = 0; b < 4; b++)
#pragma unroll
                for (int q = 0; q < 4; q++) acc[a][b][q] = 0.0f;

        load_chunk(0);
        load_chunk(1);

        for (int c = 0; c < NC; c++) {
            if (c + 1 < NC) { CP_WAIT(1); }
            else            { CP_WAIT(0); }
            __syncthreads();
            if (c + 2 < NC) load_chunk(c + 2);

            const uint32_t sbuf = sb + SM_BUF + (uint32_t)(c % NBUF) * BUFSZ;
#pragma unroll
            for (int ks = 0; ks < BK / 16; ks++) {
                uint32_t ah[4][4];
                const uint32_t aoff =
                    (uint32_t)(((2 * ks + a_chsel) ^ axr) << 4);
#pragma unroll
                for (int mi = 0; mi < 4; mi++) {
                    uint32_t addr = sbuf + a_rowoff +
                                    (uint32_t)mi * 2048u + aoff;
                    ldm_x4(ah[mi], addr);
                }
                const uint32_t boff =
                    (uint32_t)(((2 * ks + b_chsel) ^ bxr) << 4);
#pragma unroll
                for (int jp = 0; jp < 2; jp++) {
                    uint32_t baddr = sbuf + b_rowoff +
                                     (uint32_t)jp * 2048u + boff;
                    uint32_t bh[4];
                    ldm_x4(bh, baddr);
#pragma unroll
                    for (int mi = 0; mi < 4; mi++) {
                        mma16816(acc[mi][2 * jp],     ah[mi], bh[0], bh[1]);
                        mma16816(acc[mi][2 * jp + 1], ah[mi], bh[2], bh[3]);
                    }
                }
            }
        }

        // ---- epilogue -----------------------------------------------------
        const float* bias = Bv + (size_t)e * NDIM;
#pragma unroll
        for (int mi = 0; mi < 4; mi++) {
            const int lr0 = wm * 64 + mi * 16 + g;
            const int slotA = Srow[lr0];
            const int slotB = Srow[lr0 + 8];
#pragma unroll
            for (int nj = 0; nj < 4; nj++) {
                const int col = n0 + wn * 32 + nj * 8 + 2 * tg;
                const float b0 = bias[col], b1 = bias[col + 1];
                if (FFN1) {
                    if (slotA >= 0) {
                        float v0 = acc[mi][nj][0] + b0;
                        float v1 = acc[mi][nj][1] + b1;
                        v0 = 0.5f * v0 *
                             (1.0f + erff(v0 * 0.7071067811865475f));
                        v1 = 0.5f * v1 *
                             (1.0f + erff(v1 * 0.7071067811865475f));
                        *(__half2*)(d_hs + (size_t)slotA * INTER + col) =
                            __floats2half2_rn(v0, v1);
                    }
                    if (slotB >= 0) {
                        float v0 = acc[mi][nj][2] + b0;
                        float v1 = acc[mi][nj][3] + b1;
                        v0 = 0.5f * v0 *
                             (1.0f + erff(v0 * 0.7071067811865475f));
                        v1 = 0.5f * v1 *
                             (1.0f + erff(v1 * 0.7071067811865475f));
                        *(__half2*)(d_hs + (size_t)slotB * INTER + col) =
                            __floats2half2_rn(v0, v1);
                    }
                } else {
                    if (slotA >= 0) {
                        float wmul = d_slot_w[slotA];
                        float2 o;
                        o.x = (acc[mi][nj][0] + b0) * wmul;
                        o.y = (acc[mi][nj][1] + b1) * wmul;
                        *(float2*)(d_y + (size_t)slotA * HID + col) = o;
                    }
                    if (slotB >= 0) {
                        float wmul = d_slot_w[slotB];
                        float2 o;
                        o.x = (acc[mi][nj][2] + b0) * wmul;
                        o.y = (acc[mi][nj][3] + b1) * wmul;
                        *(float2*)(d_y + (size_t)slotB * HID + col) = o;
                    }
                }
            }
        }
    }
}

// ------------------------------ combine ------------------------------------

__global__ void combine_kernel(float* __restrict__ out, int T) {
    int i = blockIdx.x * blockDim.x + threadIdx.x;
    int total = T * (HID / 4);
    if (i >= total) return;
    int h4 = i & (HID / 4 - 1);
    int t  = i >> 8;
    const float4* y4 = (const float4*)d_y;
    float4 a = y4[(size_t)(2 * t) * (HID / 4) + h4];
    float4 b = y4[(size_t)(2 * t + 1) * (HID / 4) + h4];
    float4 r;
    r.x = a.x + b.x; r.y = a.y + b.y; r.z = a.z + b.z; r.w = a.w + b.w;
    ((float4*)out)[i] = r;
}

// ------------------------------- launch ------------------------------------

extern "C" void kernel_launch(void* const* d_in, const int* in_sizes, int n_in,
                              void* d_out, int out_size) {
    const float* x  = (const float*)d_in[0];
    const float* gw = (const float*)d_in[1];
    const float* W1 = (const float*)d_in[2];
    const float* b1 = (const float*)d_in[3];
    const float* W2 = (const float*)d_in[4];
    const float* b2 = (const float*)d_in[5];
    float* out = (float*)d_out;

    int T = in_sizes[0] / HID;

    cudaFuncSetAttribute(moe_gemm_mma<HID, INTER, true>,
                         cudaFuncAttributeMaxDynamicSharedMemorySize,
                         SMEM_TOTAL);
    cudaFuncSetAttribute(moe_gemm_mma<INTER, HID, false>,
                         cudaFuncAttributeMaxDynamicSharedMemorySize,
                         SMEM_TOTAL);

    __half* dxs; cudaGetSymbolAddress((void**)&dxs, d_xs);
    __half* dw1; cudaGetSymbolAddress((void**)&dw1, d_w1h);
    __half* dw2; cudaGetSymbolAddress((void**)&dw2, d_w2h);

    size_t nx4 = (size_t)T * HID / 4;
    size_t nw4 = WCNT / 4;

    // launch 0: x -> fp16 (+ zero counts & work counters)
    split_kernel<<<(unsigned)((nx4 + 255) / 256), 256>>>(x, dxs, nx4, 1);
    // launch 1: W1 & W2 -> fp16 (fused)
    split_w_dual<<<(unsigned)((2 * nw4 + 255) / 256), 256>>>(W1, dw1, W2, dw2,
                                                             nw4);
    // launch 2: gating
    gate_kernel<<<(T + 7) / 8, 256>>>(x, gw, T);
    // launch 3: GEMM1, persistent  (ncu target)
    moe_gemm_mma<HID, INTER, true><<<NPERSIST, 256, SMEM_TOTAL>>>(b1);
    // launch 4: GEMM2, persistent
    moe_gemm_mma<INTER, HID, false><<<NPERSIST, 256, SMEM_TOTAL>>>(b2);
    // launch 5: combine
    combine_kernel<<<(T * (HID / 4) + 255) / 256, 256>>>(out, T);
}

// round 15
// speedup vs baseline: 1.1486x; 1.0097x over previous
#include <cuda_runtime.h>
#include <cuda_bf16.h>
#include <cuda_fp16.h>
#include <math.h>
#include <stdint.h>

// ---------------------------------------------------------------------------
// MoE FFN top-2/8, H=1024, I=4096, T<=8192, fp32 in/out.
// R15: persistent GEMM1 whose work queue interleaves 1024 W2-split slices
// (fp32->fp16, DRAM-bound) with GEMM tiles (issue-bound) at a 1:4 ratio —
// the W2 conversion rides inside GEMM1's idle DRAM. GEMM inner loop = R11
// (128x128 CTA, 64x32 warp tile, 2 CTAs/SM, 3-buffer cp.async ring).
// Kahan gate. Launch order: split_x(0), split_w1(1), gate(2),
// gemm1(3 = ncu target), gemm2(4), combine(5).
// ---------------------------------------------------------------------------

#define HID   1024
#define INTER 4096
#define NEXP  8
#define TMAX  8192
#define NSLOT (2 * TMAX)

#define WCNT ((size_t)NEXP * (size_t)INTER * (size_t)HID)
#define XOFF ((size_t)TMAX * (size_t)HID)
#define HOFF ((size_t)NSLOT * (size_t)INTER)

#define NSPLIT  1024                  // W2 slices: 33.5M elems / 32768
#define SLICE4  8192                  // float4 per slice

__device__ __half d_xs[XOFF];         // x fp16
__device__ __half d_w1h[WCNT];        // W1 fp16
__device__ __half d_w2h[WCNT];        // W2 fp16
__device__ __half d_hs[HOFF];         // h fp16
__device__ float  d_y[(size_t)NSLOT * (size_t)HID];
__device__ float  d_slot_w[NSLOT];
__device__ int    d_slot_list[NEXP * TMAX];
__device__ int    d_counts[NEXP];
__device__ int    d_work1;
__device__ int    d_work2;

// ------------------------------ PTX helpers --------------------------------

__device__ __forceinline__ uint32_t smem_u32(const void* p) {
    uint32_t a;
    asm("{ .reg .u64 t; cvta.to.shared.u64 t, %1; cvt.u32.u64 %0, t; }"
        : "=r"(a) : "l"(p));
    return a;
}

__device__ __forceinline__ void cp16(uint32_t saddr, const void* g) {
    asm volatile("cp.async.cg.shared.global [%0], [%1], 16;"
                 :: "r"(saddr), "l"(g));
}
#define CP_COMMIT() asm volatile("cp.async.commit_group;" ::: "memory")
#define CP_WAIT(N)  asm volatile("cp.async.wait_group %0;" :: "n"(N) : "memory")

__device__ __forceinline__ void ldm_x4(uint32_t* r, uint32_t addr) {
    asm volatile("ldmatrix.sync.aligned.m8n8.x4.shared.b16 {%0,%1,%2,%3}, [%4];"
                 : "=r"(r[0]), "=r"(r[1]), "=r"(r[2]), "=r"(r[3]) : "r"(addr));
}

__device__ __forceinline__ void mma16816(float* c, const uint32_t* a,
                                         uint32_t b0, uint32_t b1) {
    asm volatile(
        "mma.sync.aligned.m16n8k16.row.col.f32.f16.f16.f32 "
        "{%0,%1,%2,%3}, {%4,%5,%6,%7}, {%8,%9}, {%0,%1,%2,%3};"
        : "+f"(c[0]), "+f"(c[1]), "+f"(c[2]), "+f"(c[3])
        : "r"(a[0]), "r"(a[1]), "r"(a[2]), "r"(a[3]), "r"(b0), "r"(b1));
}

__device__ __forceinline__ ushort4 cvt4h(float4 v) {
    return make_ushort4(__half_as_ushort(__float2half_rn(v.x)),
                        __half_as_ushort(__float2half_rn(v.y)),
                        __half_as_ushort(__float2half_rn(v.z)),
                        __half_as_ushort(__float2half_rn(v.w)));
}

// ---------------------------- split kernels --------------------------------

__global__ void split_kernel(const float* __restrict__ src,
                             __half* __restrict__ dst, size_t n4,
                             int zero_state) {
    if (zero_state && blockIdx.x == 0 && threadIdx.x < NEXP + 2) {
        if (threadIdx.x < NEXP) d_counts[threadIdx.x] = 0;
        else if (threadIdx.x == NEXP) d_work1 = 0;
        else d_work2 = 0;
    }
    size_t i = (size_t)blockIdx.x * blockDim.x + threadIdx.x;
    if (i >= n4) return;
    ((ushort4*)dst)[i] = cvt4h(((const float4*)src)[i]);
}

// ------------------------------ gating -------------------------------------

__global__ void gate_kernel(const float* __restrict__ x,
                            const float* __restrict__ gw, int T) {
    int warp = (blockIdx.x * blockDim.x + threadIdx.x) >> 5;
    int lane = threadIdx.x & 31;
    if (warp >= T) return;
    const float* xr = x + (size_t)warp * HID;

    float acc[NEXP], cmp[NEXP];
#pragma unroll
    for (int e = 0; e < NEXP; e++) { acc[e] = 0.0f; cmp[e] = 0.0f; }
#pragma unroll 4
    for (int i = lane; i < HID; i += 32) {
        float xv = xr[i];
#pragma unroll
        for (int e = 0; e < NEXP; e++) {
            float prod = xv * gw[e * HID + i];
            float y = prod - cmp[e];
            float t = acc[e] + y;
            cmp[e] = (t - acc[e]) - y;
            acc[e] = t;
        }
    }
#pragma unroll
    for (int e = 0; e < NEXP; e++) {
#pragma unroll
        for (int o = 16; o > 0; o >>= 1)
            acc[e] += __shfl_down_sync(0xffffffffu, acc[e], o);
    }
    if (lane == 0) {
        float bv = -1e30f, sv = -1e30f;
        int bi = 0, si = 0;
#pragma unroll
        for (int e = 0; e < NEXP; e++) {
            float val = acc[e];
            if (val > bv) { sv = bv; si = bi; bv = val; bi = e; }
            else if (val > sv) { sv = val; si = e; }
        }
        float e1 = expf(sv - bv);
        float s = 1.0f + e1;
        d_slot_w[2 * warp + 0] = 1.0f / s;
        d_slot_w[2 * warp + 1] = e1 / s;
        int p0 = atomicAdd(&d_counts[bi], 1);
        d_slot_list[bi * TMAX + p0] = 2 * warp;
        int p1 = atomicAdd(&d_counts[si], 1);
        d_slot_list[si * TMAX + p1] = 2 * warp + 1;
    }
}

// ----------------------------- HMMA GEMM -----------------------------------
// Persistent; GEMM1's queue interleaves W2-split slices (id%5==4, first 5120
// ids) with GEMM tiles. Inner loop = R11.

#define BM 128
#define BN 128
#define BK 64

#define SM_BUF 1024
#define AREG   16384
#define BOFF   AREG
#define BUFSZ  (AREG + 16384)         // 32768
#define NBUF   3
#define SMEM_TOTAL (SM_BUF + NBUF * BUFSZ)   // 99328 B; x2 CTAs = 194 KB/SM

#define NPERSIST 296

template <int KDIM, int NDIM, bool FFN1>
__global__ void __launch_bounds__(256, 2)
moe_gemm_mma(const float* __restrict__ Bv,       // bias [NEXP][NDIM]
             const float* __restrict__ Wsrc)     // W2 fp32 (FFN1 only)
{
    constexpr int NC = KDIM / BK;
    constexpr int NT = NDIM / BN;

    const __half* __restrict__ Wbase = FFN1 ? d_w1h : d_w2h;
    const __half* __restrict__ Abase = FFN1 ? d_xs : d_hs;

    extern __shared__ __align__(128) char smem[];
    const uint32_t sb = smem_u32(smem);
    const int tid = threadIdx.x;

    int* Srow   = (int*)smem;                 // [0, 512)
    int* s_tile = (int*)(smem + 512);

    int mt[NEXP];
    int total_tiles = 0;
#pragma unroll
    for (int e = 0; e < NEXP; e++) {
        mt[e] = (d_counts[e] + BM - 1) / BM;
        total_tiles += mt[e] * NT;
    }
    // total_tiles >= 4096 always (sum ceil >= 128 M-tiles, NT = 32) for FFN1,
    // so all NSPLIT split ids (4,9,...,5119) are < total_ids.
    const int total_ids = total_tiles + (FFN1 ? NSPLIT : 0);
    int* counter = FFN1 ? &d_work1 : &d_work2;

    // ---- compute-side constants ------------------------------------------
    const int wid = tid >> 5, l = tid & 31;
    const int wm = wid >> 2;
    const int wn = wid & 3;
    const int g  = l >> 2, tg = l & 3;

    const int arow0 = wm * 64 + (l & 15);
    const uint32_t a_rowoff = (uint32_t)arow0 * 128u;
    const int axr = arow0 & 7;
    const int a_chsel = l >> 4;

    const int brow0 = wn * 32 + ((l >> 4) << 3) + (l & 7);
    const uint32_t b_rowoff = BOFF + (uint32_t)brow0 * 128u;
    const int bxr = brow0 & 7;
    const int b_chsel = (l >> 3) & 1;

    const int lrow = tid >> 1;
    const int ach0 = (tid & 1) * 4;
    const uint32_t row_dst = (uint32_t)lrow * 128u;
    const int rx = lrow & 7;

    while (true) {
        if (tid == 0) *s_tile = atomicAdd(counter, 1);
        __syncthreads();                  // also: prev iter done with Srow
        const int id = *s_tile;
        if (id >= total_ids) break;

        int t;
        if (FFN1) {
            if (id < 5 * NSPLIT) {
                if ((id % 5) == 4) {
                    // ---- W2 split slice ----
                    const int sidx = id / 5;
                    const float4* src =
                        (const float4*)Wsrc + (size_t)sidx * SLICE4 + tid;
                    ushort4* dst =
                        (ushort4*)d_w2h + (size_t)sidx * SLICE4 + tid;
#pragma unroll 8
                    for (int k = 0; k < 32; k++)
                        dst[k * 256] = cvt4h(src[k * 256]);
                    continue;
                }
                t = id - (id + 1) / 5;    // tiles before id
            } else {
                t = id - NSPLIT;
            }
        } else {
            t = id;
        }

        // map t -> (e, m, n); m fastest so consecutive tiles share B
        int e = 0;
#pragma unroll
        for (int k = 0; k < NEXP - 1; k++) {
            int sz = mt[e] * NT;
            if (t >= sz) { t -= sz; e++; }
        }
        const int m  = t % mt[e];
        const int n  = t / mt[e];
        const int r0 = m * BM;
        const int n0 = n * BN;
        const int cnt = d_counts[e];

        if (tid < BM) {
            int idx = r0 + tid;
            Srow[tid] = (idx < cnt) ? d_slot_list[e * TMAX + idx] : -1;
        }
        __syncthreads();

        int s_ld = Srow[lrow];
        const __half* aptr;
        if (FFN1) {
            int tok = (s_ld < 0) ? 0 : (s_ld >> 1);
            aptr = Abase + (size_t)tok * KDIM;
        } else {
            aptr = Abase + (size_t)(s_ld < 0 ? 0 : s_ld) * KDIM;
        }
        const __half* bptr = Wbase + ((size_t)e * NDIM + n0 + lrow) * KDIM;

        auto load_chunk = [&](int c) {
            const uint32_t dbuf = sb + SM_BUF + (uint32_t)(c % NBUF) * BUFSZ;
            const int koff = c * BK;
#pragma unroll
            for (int i = 0; i < 4; i++) {
                int ch = ach0 + i;
                uint32_t sw = (uint32_t)((ch ^ rx) << 4);
                cp16(dbuf + row_dst + sw, aptr + koff + ch * 8);
                cp16(dbuf + BOFF + row_dst + sw, bptr + koff + ch * 8);
            }
            CP_COMMIT();
        };

        float acc[4][4][4];
#pragma unroll
        for (int a = 0; a < 4; a++)
#pragma unroll
            for (int b = 0; b < 4; b++)
#pragma unroll
                for (int q = 0; q < 4; q++) acc[a][b][q] = 0.0f;

        load_chunk(0);
        load_chunk(1);

        for (int c = 0; c < NC; c++) {
            if (c + 1 < NC) { CP_WAIT(1); }
            else            { CP_WAIT(0); }
            __syncthreads();
            if (c + 2 < NC) load_chunk(c + 2);

            const uint32_t sbuf = sb + SM_BUF + (uint32_t)(c % NBUF) * BUFSZ;
#pragma unroll
            for (int ks = 0; ks < BK / 16; ks++) {
                uint32_t ah[4][4];
                const uint32_t aoff =
                    (uint32_t)(((2 * ks + a_chsel) ^ axr) << 4);
#pragma unroll
                for (int mi = 0; mi < 4; mi++) {
                    uint32_t addr = sbuf + a_rowoff +
                                    (uint32_t)mi * 2048u + aoff;
                    ldm_x4(ah[mi], addr);
                }
                const uint32_t boff =
                    (uint32_t)(((2 * ks + b_chsel) ^ bxr) << 4);
#pragma unroll
                for (int jp = 0; jp < 2; jp++) {
                    uint32_t baddr = sbuf + b_rowoff +
                                     (uint32_t)jp * 2048u + boff;
                    uint32_t bh[4];
                    ldm_x4(bh, baddr);
#pragma unroll
                    for (int mi = 0; mi < 4; mi++) {
                        mma16816(acc[mi][2 * jp],     ah[mi], bh[0], bh[1]);
                        mma16816(acc[mi][2 * jp + 1], ah[mi], bh[2], bh[3]);
                    }
                }
            }
        }

        // ---- epilogue -----------------------------------------------------
        const float* bias = Bv + (size_t)e * NDIM;
#pragma unroll
        for (int mi = 0; mi < 4; mi++) {
            const int lr0 = wm * 64 + mi * 16 + g;
            const int slotA = Srow[lr0];
            const int slotB = Srow[lr0 + 8];
#pragma unroll
            for (int nj = 0; nj < 4; nj++) {
                const int col = n0 + wn * 32 + nj * 8 + 2 * tg;
                const float b0 = bias[col], b1 = bias[col + 1];
                if (FFN1) {
                    if (slotA >= 0) {
                        float v0 = acc[mi][nj][0] + b0;
                        float v1 = acc[mi][nj][1] + b1;
                        v0 = 0.5f * v0 *
                             (1.0f + erff(v0 * 0.7071067811865475f));
                        v1 = 0.5f * v1 *
                             (1.0f + erff(v1 * 0.7071067811865475f));
                        *(__half2*)(d_hs + (size_t)slotA * INTER + col) =
                            __floats2half2_rn(v0, v1);
                    }
                    if (slotB >= 0) {
                        float v0 = acc[mi][nj][2] + b0;
                        float v1 = acc[mi][nj][3] + b1;
                        v0 = 0.5f * v0 *
                             (1.0f + erff(v0 * 0.7071067811865475f));
                        v1 = 0.5f * v1 *
                             (1.0f + erff(v1 * 0.7071067811865475f));
                        *(__half2*)(d_hs + (size_t)slotB * INTER + col) =
                            __floats2half2_rn(v0, v1);
                    }
                } else {
                    if (slotA >= 0) {
                        float wmul = d_slot_w[slotA];
                        float2 o;
                        o.x = (acc[mi][nj][0] + b0) * wmul;
                        o.y = (acc[mi][nj][1] + b1) * wmul;
                        *(float2*)(d_y + (size_t)slotA * HID + col) = o;
                    }
                    if (slotB >= 0) {
                        float wmul = d_slot_w[slotB];
                        float2 o;
                        o.x = (acc[mi][nj][2] + b0) * wmul;
                        o.y = (acc[mi][nj][3] + b1) * wmul;
                        *(float2*)(d_y + (size_t)slotB * HID + col) = o;
                    }
                }
            }
        }
    }
}

// ------------------------------ combine ------------------------------------

__global__ void combine_kernel(float* __restrict__ out, int T) {
    int i = blockIdx.x * blockDim.x + threadIdx.x;
    int total = T * (HID / 4);
    if (i >= total) return;
    int h4 = i & (HID / 4 - 1);
    int t  = i >> 8;
    const float4* y4 = (const float4*)d_y;
    float4 a = y4[(size_t)(2 * t) * (HID / 4) + h4];
    float4 b = y4[(size_t)(2 * t + 1) * (HID / 4) + h4];
    float4 r;
    r.x = a.x + b.x; r.y = a.y + b.y; r.z = a.z + b.z; r.w = a.w + b.w;
    ((float4*)out)[i] = r;
}

// ------------------------------- launch ------------------------------------

extern "C" void kernel_launch(void* const* d_in, const int* in_sizes, int n_in,
                              void* d_out, int out_size) {
    const float* x  = (const float*)d_in[0];
    const float* gw = (const float*)d_in[1];
    const float* W1 = (const float*)d_in[2];
    const float* b1 = (const float*)d_in[3];
    const float* W2 = (const float*)d_in[4];
    const float* b2 = (const float*)d_in[5];
    float* out = (float*)d_out;

    int T = in_sizes[0] / HID;

    cudaFuncSetAttribute(moe_gemm_mma<HID, INTER, true>,
                         cudaFuncAttributeMaxDynamicSharedMemorySize,
                         SMEM_TOTAL);
    cudaFuncSetAttribute(moe_gemm_mma<INTER, HID, false>,
                         cudaFuncAttributeMaxDynamicSharedMemorySize,
                         SMEM_TOTAL);

    __half* dxs; cudaGetSymbolAddress((void**)&dxs, d_xs);
    __half* dw1; cudaGetSymbolAddress((void**)&dw1, d_w1h);

    size_t nx4 = (size_t)T * HID / 4;
    size_t nw4 = WCNT / 4;

    // launch 0: x -> fp16 (+ zero counts & work counters)
    split_kernel<<<(unsigned)((nx4 + 255) / 256), 256>>>(x, dxs, nx4, 1);
    // launch 1: W1 -> fp16 (W2 handled inside GEMM1's work queue)
    split_kernel<<<(unsigned)((nw4 + 255) / 256), 256>>>(W1, dw1, nw4, 0);
    // launch 2: gating
    gate_kernel<<<(T + 7) / 8, 256>>>(x, gw, T);
    // launch 3: GEMM1, persistent, with interleaved W2 split  (ncu target)
    moe_gemm_mma<HID, INTER, true><<<NPERSIST, 256, SMEM_TOTAL>>>(b1, W2);
    // launch 4: GEMM2, persistent
    moe_gemm_mma<INTER, HID, false><<<NPERSIST, 256, SMEM_TOTAL>>>(b2, W2);
    // launch 5: combine
    combine_kernel<<<(T * (HID / 4) + 255) / 256, 256>>>(out, T);
}